// round 11
// baseline (speedup 1.0000x reference)
#include <cuda_runtime.h>
#include <cuda_bf16.h>

typedef unsigned long long u64;

#define NQ 11
#define NDIM 2048                 // 1 << NQ
#define NLAYERS 5
#define NBLK (NLAYERS + 1)        // 6 YZY blocks
#define NMAT (NBLK * NQ)          // 66 fused matrices
#define W_SIZE (3 * NMAT)         // 198

// ---------- packed f32x2 helpers (FFMA2 is PTX-only on sm_103a) ----------
__device__ __forceinline__ u64 pk(float lo, float hi) {
    u64 r; asm("mov.b64 %0, {%1, %2};" : "=l"(r) : "f"(lo), "f"(hi)); return r;
}
__device__ __forceinline__ void upk(u64 v, float& lo, float& hi) {
    asm("mov.b64 {%0, %1}, %2;" : "=f"(lo), "=f"(hi) : "l"(v));
}
__device__ __forceinline__ u64 swp(u64 v) {
    float lo, hi; upk(v, lo, hi); return pk(hi, lo);
}
__device__ __forceinline__ u64 fma2(u64 a, u64 b, u64 c) {
    u64 r; asm("fma.rn.f32x2 %0, %1, %2, %3;" : "=l"(r) : "l"(a), "l"(b), "l"(c)); return r;
}
__device__ __forceinline__ u64 mul2(u64 a, u64 b) {
    u64 r; asm("mul.rn.f32x2 %0, %1, %2;" : "=l"(r) : "l"(a), "l"(b)); return r;
}

__device__ __forceinline__ float2 cmul(float2 a, float2 b) {
    return make_float2(a.x * b.x - a.y * b.y, a.x * b.y + a.y * b.x);
}

// ---------- Compile-time GF(2) CNOT-ring tracking ----------
struct Tabs {
    unsigned v[NLAYERS][NQ];   // gate-axis XOR vectors (G columns) per layer/qubit
    unsigned g[NQ];            // final G columns (trace permutation)
};
constexpr Tabs make_tabs() {
    Tabs T{};
    unsigned frow[NQ]{}, gcol[NQ]{};
    for (int i = 0; i < NQ; i++) { frow[i] = 1u << i; gcol[i] = 1u << i; }
    for (int L = 0; L < NLAYERS; L++) {
        for (int q = 0; q < NQ; q++) {
            const int bc = NQ - 1 - q;
            const int bt = NQ - 1 - ((q + 1) % NQ);
            frow[bt] ^= frow[bc];
            gcol[bc] ^= gcol[bt];
        }
        for (int q = 0; q < NQ; q++) T.v[L][q] = gcol[NQ - 1 - q];
    }
    for (int i = 0; i < NQ; i++) T.g[i] = gcol[i];
    return T;
}
constexpr Tabs TB = make_tabs();            // compile-time folded constants
__constant__ Tabs dTB = make_tabs();        // device mirror for runtime accesses

__device__ __forceinline__ int decode_dimA(const int* p, int B, int out_size) {
    int d = -1;
    if (p) {
        int v = p[0];
        if (v >= 1 && v <= NQ) d = v;
        else {
            float f = __int_as_float(v);
            if (f >= 0.5f && f <= 11.5f) d = (int)(f + 0.5f);
        }
    }
    if (d < 1 || d > NQ) {
        for (int t = 1; t <= NQ; t++) {
            long long nc = (long long)B << (2 * t);
            if (nc == (long long)out_size || 2 * nc == (long long)out_size) { d = t; break; }
        }
    }
    if (d < 1 || d > NQ) d = 5;
    return d;
}

// Packed gate splats, indices: 0=axx 1=ayy 2=cayy 3=bxx 4=byy 5=nbxx
// SU(2) gate M = [[al, -conj(be)], [be, conj(al)]]:
//   al*z       = axx*z  + ayy*swp(z)      axx=(al.x,al.x)  ayy=(-al.y, al.y)
//   conj(al)*z = axx*z  + cayy*swp(z)     cayy=(al.y,-al.y)
//   be*z       = bxx*z  + byy*swp(z)      bxx=(be.x,be.x)  byy=(-be.y, be.y)
//  -conj(be)*z = nbxx*z + byy*swp(z)      nbxx=(-be.x,-be.x)
__device__ __forceinline__ void reg_gate(u64& za, u64& zb, const u64* G) {
    u64 zas = swp(za), zbs = swp(zb);
    u64 na = fma2(G[4], zbs, fma2(G[5], zb, fma2(G[1], zas, mul2(G[0], za))));
    u64 nb = fma2(G[2], zbs, fma2(G[0], zb, fma2(G[4], zas, mul2(G[3], za))));
    za = na; zb = nb;
}

template<int MASK>
__device__ __forceinline__ void lane_gate2(u64 z[2], const u64* G, int lane) {
    bool bit = (lane & MASK) != 0;
    u64 cxx = G[0];                     // al.x == conj(al).x
    u64 cyy = bit ? G[2] : G[1];        // conj(al) : al
    u64 dxx = bit ? G[3] : G[5];        // be : -conj(be)
    u64 dyy = G[4];                     // shared
    #pragma unroll
    for (int k = 0; k < 2; k++) {
        float lo, hi; upk(z[k], lo, hi);
        float plo = __shfl_xor_sync(0xffffffffu, lo, MASK);
        float phi = __shfl_xor_sync(0xffffffffu, hi, MASK);
        u64 zp = pk(plo, phi);
        z[k] = fma2(dyy, swp(zp), fma2(dxx, zp, fma2(cyy, swp(z[k]), mul2(cxx, z[k]))));
    }
}

// One YZY block (block L+1) in y-coordinates with 1024 threads, 2 amps/thread.
// Round 1: y0 = register bit; y1..y5 = lane bits; y6..y10 = warp bits (gates q0..q5).
// Round 2: y6 = register bit; y7..y10,y0 = lane bits; y1..y5 = warp bits (gates q6..q10).
template<int L>
__device__ __forceinline__ void do_layer(u64* st, const u64 (*pg)[6], int tid) {
    constexpr unsigned v0 = TB.v[L][0],  v1 = TB.v[L][1],  v2 = TB.v[L][2];
    constexpr unsigned v3 = TB.v[L][3],  v4 = TB.v[L][4],  v5 = TB.v[L][5];
    constexpr unsigned v6 = TB.v[L][6],  v7 = TB.v[L][7],  v8 = TB.v[L][8];
    constexpr unsigned v9 = TB.v[L][9],  v10 = TB.v[L][10];
    const int lane = tid & 31, wrp = tid >> 5;
    const int mb = (L + 1) * NQ;
    u64 z[2];

    // ---- Round 1 ----
    {
        unsigned base = ((lane & 1) ? v1 : 0u) ^ ((lane & 2) ? v2 : 0u)
                      ^ ((lane & 4) ? v3 : 0u) ^ ((lane & 8) ? v4 : 0u)
                      ^ ((lane & 16) ? v5 : 0u)
                      ^ ((wrp & 1) ? v6 : 0u) ^ ((wrp & 2) ? v7 : 0u)
                      ^ ((wrp & 4) ? v8 : 0u) ^ ((wrp & 8) ? v9 : 0u)
                      ^ ((wrp & 16) ? v10 : 0u);
        unsigned a0 = base, a1 = base ^ v0;
        z[0] = st[a0]; z[1] = st[a1];
        reg_gate(z[0], z[1], pg[mb + 0]);
        lane_gate2<1 >(z, pg[mb + 1], lane);
        lane_gate2<2 >(z, pg[mb + 2], lane);
        lane_gate2<4 >(z, pg[mb + 3], lane);
        lane_gate2<8 >(z, pg[mb + 4], lane);
        lane_gate2<16>(z, pg[mb + 5], lane);
        st[a0] = z[0]; st[a1] = z[1];
        __syncthreads();
    }
    // ---- Round 2 ----
    {
        unsigned base = ((lane & 1) ? v7 : 0u) ^ ((lane & 2) ? v8 : 0u)
                      ^ ((lane & 4) ? v9 : 0u) ^ ((lane & 8) ? v10 : 0u)
                      ^ ((lane & 16) ? v0 : 0u)
                      ^ ((wrp & 1) ? v1 : 0u) ^ ((wrp & 2) ? v2 : 0u)
                      ^ ((wrp & 4) ? v3 : 0u) ^ ((wrp & 8) ? v4 : 0u)
                      ^ ((wrp & 16) ? v5 : 0u);
        unsigned a0 = base, a1 = base ^ v6;
        z[0] = st[a0]; z[1] = st[a1];
        reg_gate(z[0], z[1], pg[mb + 6]);
        lane_gate2<1>(z, pg[mb + 7],  lane);
        lane_gate2<2>(z, pg[mb + 8],  lane);
        lane_gate2<4>(z, pg[mb + 9],  lane);
        lane_gate2<8>(z, pg[mb + 10], lane);
        st[a0] = z[0]; st[a1] = z[1];
        __syncthreads();
    }
}

__global__ __launch_bounds__(1024, 1)
void qsim_kernel(const float* __restrict__ x,
                 const float* __restrict__ w,
                 const int* __restrict__ dimA_p,
                 void* __restrict__ out_v,
                 int B, int out_size)
{
    __shared__ u64 st[NDIM];                    // packed statevector (16 KB)
    __shared__ u64 pg[NMAT][6];                 // packed gate splats (3.1 KB)
    __shared__ float2 u[NQ][2];                 // embed*YZY0 column coefs
    __shared__ int physA[32], physB[64];        // trace index tables
    __shared__ float partial[4][1024];          // trace partials (16 KB)

    const int tid = threadIdx.x;
    const int b   = blockIdx.x;

    // ---- Fused M = Ry(t2) Rz(t1) Ry(t0); store packed splats ----
    float2 al0, be0;                            // kept for embedding (tid < NQ)
    if (tid < NMAT) {
        int base = tid * 3;
        float t0 = w[base], t1 = w[base + 1], t2 = w[base + 2];
        float c0, s0, c1, s1, c2, s2;
        sincosf(0.5f * t0, &s0, &c0);
        sincosf(0.5f * t1, &s1, &c1);
        sincosf(0.5f * t2, &s2, &c2);
        float2 em = make_float2(c1, -s1);
        float2 ep = make_float2(c1,  s1);
        float2 al = make_float2( c2*c0*em.x - s2*s0*ep.x,  c2*c0*em.y - s2*s0*ep.y);
        float2 be = make_float2( s2*c0*em.x + c2*s0*ep.x,  s2*c0*em.y + c2*s0*ep.y);
        pg[tid][0] = pk(al.x, al.x);
        pg[tid][1] = pk(-al.y, al.y);
        pg[tid][2] = pk(al.y, -al.y);
        pg[tid][3] = pk(be.x, be.x);
        pg[tid][4] = pk(-be.y, be.y);
        pg[tid][5] = pk(-be.x, -be.x);
        al0 = al; be0 = be;
    }
    // ---- Embedding fused into block 0 ----
    if (tid < NQ) {
        float sh, ch;
        sincosf(0.5f * x[b * NQ + tid], &sh, &ch);
        u[tid][0] = make_float2(al0.x * ch - be0.x * sh, al0.y * ch + be0.y * sh);
        u[tid][1] = make_float2(be0.x * ch + al0.x * sh, be0.y * ch - al0.y * sh);
    }
    // ---- Trace permutation tables ----
    if (tid >= 64 && tid < 96) {
        int j = tid - 64; unsigned ph = 0;
        #pragma unroll
        for (int bit = 0; bit < 5; bit++) if ((j >> bit) & 1) ph ^= dTB.g[bit];
        physA[j] = (int)ph;
    }
    if (tid < 64) {
        int i = tid; unsigned ph = 0;
        #pragma unroll
        for (int bit = 0; bit < 6; bit++) if ((i >> bit) & 1) ph ^= dTB.g[5 + bit];
        physB[i] = (int)ph;
    }
    __syncthreads();

    // ---- Product-state init: 2 consecutive amps per thread ----
    {
        // p = (tid << 1) | k ; qubit q <-> bit (10 - q)
        float2 hi = cmul(u[0][(tid >> 9) & 1], u[1][(tid >> 8) & 1]);
        hi = cmul(hi, u[2][(tid >> 7) & 1]);
        hi = cmul(hi, u[3][(tid >> 6) & 1]);
        hi = cmul(hi, u[4][(tid >> 5) & 1]);
        hi = cmul(hi, u[5][(tid >> 4) & 1]);
        hi = cmul(hi, u[6][(tid >> 3) & 1]);
        hi = cmul(hi, u[7][(tid >> 2) & 1]);
        hi = cmul(hi, u[8][(tid >> 1) & 1]);
        hi = cmul(hi, u[9][tid & 1]);
        #pragma unroll
        for (int k = 0; k < 2; k++) {
            float2 r = cmul(hi, u[10][k]);
            st[(tid << 1) | k] = pk(r.x, r.y);
        }
    }
    __syncthreads();

    // ---- Blocks 1..5 ----
    do_layer<0>(st, pg, tid);
    do_layer<1>(st, pg, tid);
    do_layer<2>(st, pg, tid);
    do_layer<3>(st, pg, tid);
    do_layer<4>(st, pg, tid);

    // ---- Partial trace: Re(rho[j,k]) = sum_i Re(psi_ij psi_ik*) ----
    const int dimA = decode_dimA(dimA_p, B, out_size);
    const int dA   = 1 << dimA;
    const int dB   = NDIM >> dimA;
    const int nOut = dA * dA;
    const bool real_only = ((long long)B * nOut == (long long)out_size);

    if (dimA == 5 && real_only) {
        // 4 i-groups x 256 threads; each thread a 2x2 tile over 16 i's; packed dot
        int g  = tid >> 8;           // 0..3
        int ss = tid & 255;
        int j0 = (ss & 15) * 2;
        int k0 = (ss >> 4) * 2;
        int paj0 = physA[j0], paj1 = physA[j0 + 1];
        int pak0 = physA[k0], pak1 = physA[k0 + 1];
        u64 acc00 = 0ull, acc01 = 0ull, acc10 = 0ull, acc11 = 0ull;
        #pragma unroll
        for (int ii = 0; ii < 16; ii++) {
            int pb = physB[g * 16 + ii];
            u64 aj0 = st[pb ^ paj0];
            u64 aj1 = st[pb ^ paj1];
            u64 ak0 = st[pb ^ pak0];
            u64 ak1 = st[pb ^ pak1];
            acc00 = fma2(aj0, ak0, acc00);   // (x*x, y*y) lanes
            acc01 = fma2(aj0, ak1, acc01);
            acc10 = fma2(aj1, ak0, acc10);
            acc11 = fma2(aj1, ak1, acc11);
        }
        float sx, sy;
        upk(acc00, sx, sy); partial[g][j0 * 32 + k0]           = sx + sy;
        upk(acc01, sx, sy); partial[g][j0 * 32 + k0 + 1]       = sx + sy;
        upk(acc10, sx, sy); partial[g][(j0 + 1) * 32 + k0]     = sx + sy;
        upk(acc11, sx, sy); partial[g][(j0 + 1) * 32 + k0 + 1] = sx + sy;
        __syncthreads();
        ((float*)out_v)[b * 1024 + tid] =
            partial[0][tid] + partial[1][tid] + partial[2][tid] + partial[3][tid];
    } else {
        // Generic fallback (scalar)
        for (int o = tid; o < nOut; o += blockDim.x) {
            int j = o / dA;
            int k = o - j * dA;
            float2 acc = make_float2(0.f, 0.f);
            for (int i = 0; i < dB; i++) {
                int lj = i * dA + j, lk = i * dA + k;
                unsigned pj = 0, pkk = 0;
                #pragma unroll
                for (int bit = 0; bit < NQ; bit++) {
                    if ((lj >> bit) & 1) pj ^= dTB.g[bit];
                    if ((lk >> bit) & 1) pkk ^= dTB.g[bit];
                }
                float ax, ay, cx, cy;
                upk(st[pj], ax, ay);
                upk(st[pkk], cx, cy);
                acc.x = fmaf(ax, cx, fmaf(ay, cy, acc.x));
                acc.y = fmaf(ay, cx, fmaf(-ax, cy, acc.y));
            }
            if (real_only) ((float*)out_v)[b * nOut + o] = acc.x;
            else           ((float2*)out_v)[b * nOut + o] = acc;
        }
    }
}

extern "C" void kernel_launch(void* const* d_in, const int* in_sizes, int n_in,
                              void* d_out, int out_size) {
    // Bind by element count (unique sizes): w=198, dimA=1, x = B*11
    const float* x = nullptr;
    const float* w = nullptr;
    const int* dimA_p = nullptr;
    int x_size = 0;
    for (int i = 0; i < n_in; i++) {
        if (in_sizes[i] == W_SIZE) w = (const float*)d_in[i];
        else if (in_sizes[i] == 1) dimA_p = (const int*)d_in[i];
        else { x = (const float*)d_in[i]; x_size = in_sizes[i]; }
    }
    if (!x) { x = (const float*)d_in[0]; x_size = in_sizes[0]; }
    if (!w) { w = (const float*)d_in[1]; }

    int B = x_size / NQ;   // 16
    qsim_kernel<<<B, 1024>>>(x, w, dimA_p, d_out, B, out_size);
}

// round 12
// speedup vs baseline: 1.1044x; 1.1044x over previous
#include <cuda_runtime.h>
#include <cuda_bf16.h>

typedef unsigned long long u64;

#define NQ 11
#define NDIM 2048                 // 1 << NQ
#define NLAYERS 5
#define NBLK (NLAYERS + 1)        // 6 YZY blocks
#define NMAT (NBLK * NQ)          // 66 fused matrices
#define W_SIZE (3 * NMAT)         // 198

// ---------- packed f32x2 helpers (FFMA2 is PTX-only on sm_103a) ----------
__device__ __forceinline__ u64 pk(float lo, float hi) {
    u64 r; asm("mov.b64 %0, {%1, %2};" : "=l"(r) : "f"(lo), "f"(hi)); return r;
}
__device__ __forceinline__ void upk(u64 v, float& lo, float& hi) {
    asm("mov.b64 {%0, %1}, %2;" : "=f"(lo), "=f"(hi) : "l"(v));
}
__device__ __forceinline__ u64 swp(u64 v) {
    float lo, hi; upk(v, lo, hi); return pk(hi, lo);
}
__device__ __forceinline__ u64 fma2(u64 a, u64 b, u64 c) {
    u64 r; asm("fma.rn.f32x2 %0, %1, %2, %3;" : "=l"(r) : "l"(a), "l"(b), "l"(c)); return r;
}
__device__ __forceinline__ u64 mul2(u64 a, u64 b) {
    u64 r; asm("mul.rn.f32x2 %0, %1, %2;" : "=l"(r) : "l"(a), "l"(b)); return r;
}

__device__ __forceinline__ float2 cmul(float2 a, float2 b) {
    return make_float2(a.x * b.x - a.y * b.y, a.x * b.y + a.y * b.x);
}

// ---------- Compile-time GF(2) CNOT-ring tracking ----------
struct Tabs {
    unsigned v[NLAYERS][NQ];   // gate-axis XOR vectors (G columns) per layer/qubit
    unsigned g[NQ];            // final G columns (trace permutation)
};
constexpr Tabs make_tabs() {
    Tabs T{};
    unsigned frow[NQ]{}, gcol[NQ]{};
    for (int i = 0; i < NQ; i++) { frow[i] = 1u << i; gcol[i] = 1u << i; }
    for (int L = 0; L < NLAYERS; L++) {
        for (int q = 0; q < NQ; q++) {
            const int bc = NQ - 1 - q;
            const int bt = NQ - 1 - ((q + 1) % NQ);
            frow[bt] ^= frow[bc];
            gcol[bc] ^= gcol[bt];
        }
        for (int q = 0; q < NQ; q++) T.v[L][q] = gcol[NQ - 1 - q];
    }
    for (int i = 0; i < NQ; i++) T.g[i] = gcol[i];
    return T;
}
constexpr Tabs TB = make_tabs();            // compile-time folded constants
__constant__ Tabs dTB = make_tabs();        // device mirror for runtime accesses

__device__ __forceinline__ int decode_dimA(const int* p, int B, int out_size) {
    int d = -1;
    if (p) {
        int v = p[0];
        if (v >= 1 && v <= NQ) d = v;
        else {
            float f = __int_as_float(v);
            if (f >= 0.5f && f <= 11.5f) d = (int)(f + 0.5f);
        }
    }
    if (d < 1 || d > NQ) {
        for (int t = 1; t <= NQ; t++) {
            long long nc = (long long)B << (2 * t);
            if (nc == (long long)out_size || 2 * nc == (long long)out_size) { d = t; break; }
        }
    }
    if (d < 1 || d > NQ) d = 5;
    return d;
}

// Packed gate splats, indices: 0=axx 1=ayy 2=cayy 3=bxx 4=byy 5=nbxx
// SU(2) gate M = [[al, -conj(be)], [be, conj(al)]]:
//   al*z       = axx*z  + ayy*swp(z)      axx=(al.x,al.x)  ayy=(-al.y, al.y)
//   conj(al)*z = axx*z  + cayy*swp(z)     cayy=(al.y,-al.y)
//   be*z       = bxx*z  + byy*swp(z)      bxx=(be.x,be.x)  byy=(-be.y, be.y)
//  -conj(be)*z = nbxx*z + byy*swp(z)      nbxx=(-be.x,-be.x)
__device__ __forceinline__ void pair_gate(u64& za, u64& zb, const u64* G) {
    u64 zas = swp(za), zbs = swp(zb);
    u64 na = fma2(G[4], zbs, fma2(G[5], zb, fma2(G[1], zas, mul2(G[0], za))));
    u64 nb = fma2(G[2], zbs, fma2(G[0], zb, fma2(G[4], zas, mul2(G[3], za))));
    za = na; zb = nb;
}

// Register gate along stride S over 8 amps (4 independent pairs).
#define REG_GATE8(Z, G, S)                                                     \
    do {                                                                       \
        _Pragma("unroll")                                                      \
        for (int k = 0; k < 8; k++) {                                          \
            if (k & (S)) continue;                                             \
            pair_gate((Z)[k], (Z)[k + (S)], (G));                              \
        }                                                                      \
    } while (0)

template<int MASK>
__device__ __forceinline__ void lane_gate8(u64 z[8], const u64* G, int lane) {
    bool bit = (lane & MASK) != 0;
    u64 cxx = G[0];                     // al.x == conj(al).x
    u64 cyy = bit ? G[2] : G[1];        // conj(al) : al
    u64 dxx = bit ? G[3] : G[5];        // be : -conj(be)
    u64 dyy = G[4];                     // shared
    #pragma unroll
    for (int k = 0; k < 8; k++) {
        float lo, hi; upk(z[k], lo, hi);
        float plo = __shfl_xor_sync(0xffffffffu, lo, MASK);
        float phi = __shfl_xor_sync(0xffffffffu, hi, MASK);
        u64 zp = pk(plo, phi);
        z[k] = fma2(dyy, swp(zp), fma2(dxx, zp, fma2(cyy, swp(z[k]), mul2(cxx, z[k]))));
    }
}

// One YZY block (block L+1) in y-coordinates; 256 threads, 8 amps/thread.
// Round 1: y0,y1,y2 = register bits (gates q0..q2); y3..y7 = lane bits (q3..q7);
//          y8,y9,y10 = warp bits.
// Round 2: y8,y9,y10 = register bits (gates q8..q10); y0..y4 = lane bits;
//          y5,y6,y7 = warp bits. No lane gates.
template<int L>
__device__ __forceinline__ void do_layer(u64* st, const u64 (*pg)[6], int tid) {
    constexpr unsigned v0 = TB.v[L][0],  v1 = TB.v[L][1],  v2 = TB.v[L][2];
    constexpr unsigned v3 = TB.v[L][3],  v4 = TB.v[L][4],  v5 = TB.v[L][5];
    constexpr unsigned v6 = TB.v[L][6],  v7 = TB.v[L][7],  v8 = TB.v[L][8];
    constexpr unsigned v9 = TB.v[L][9],  v10 = TB.v[L][10];
    const int lane = tid & 31, wrp = tid >> 5;
    const int mb = (L + 1) * NQ;
    u64 z[8];

    // ---- Round 1 ----
    {
        unsigned base = ((lane & 1) ? v3 : 0u) ^ ((lane & 2) ? v4 : 0u)
                      ^ ((lane & 4) ? v5 : 0u) ^ ((lane & 8) ? v6 : 0u)
                      ^ ((lane & 16) ? v7 : 0u)
                      ^ ((wrp & 1) ? v8 : 0u) ^ ((wrp & 2) ? v9 : 0u)
                      ^ ((wrp & 4) ? v10 : 0u);
        unsigned addr[8];
        #pragma unroll
        for (int k = 0; k < 8; k++)
            addr[k] = base ^ ((k & 1) ? v0 : 0u) ^ ((k & 2) ? v1 : 0u)
                           ^ ((k & 4) ? v2 : 0u);
        #pragma unroll
        for (int k = 0; k < 8; k++) z[k] = st[addr[k]];
        REG_GATE8(z, pg[mb + 0], 1);
        REG_GATE8(z, pg[mb + 1], 2);
        REG_GATE8(z, pg[mb + 2], 4);
        lane_gate8<1 >(z, pg[mb + 3], lane);
        lane_gate8<2 >(z, pg[mb + 4], lane);
        lane_gate8<4 >(z, pg[mb + 5], lane);
        lane_gate8<8 >(z, pg[mb + 6], lane);
        lane_gate8<16>(z, pg[mb + 7], lane);
        #pragma unroll
        for (int k = 0; k < 8; k++) st[addr[k]] = z[k];
        __syncthreads();
    }
    // ---- Round 2: pure register gates ----
    {
        unsigned base = ((lane & 1) ? v0 : 0u) ^ ((lane & 2) ? v1 : 0u)
                      ^ ((lane & 4) ? v2 : 0u) ^ ((lane & 8) ? v3 : 0u)
                      ^ ((lane & 16) ? v4 : 0u)
                      ^ ((wrp & 1) ? v5 : 0u) ^ ((wrp & 2) ? v6 : 0u)
                      ^ ((wrp & 4) ? v7 : 0u);
        unsigned addr[8];
        #pragma unroll
        for (int k = 0; k < 8; k++)
            addr[k] = base ^ ((k & 1) ? v8 : 0u) ^ ((k & 2) ? v9 : 0u)
                           ^ ((k & 4) ? v10 : 0u);
        #pragma unroll
        for (int k = 0; k < 8; k++) z[k] = st[addr[k]];
        REG_GATE8(z, pg[mb + 8], 1);
        REG_GATE8(z, pg[mb + 9], 2);
        REG_GATE8(z, pg[mb + 10], 4);
        #pragma unroll
        for (int k = 0; k < 8; k++) st[addr[k]] = z[k];
        __syncthreads();
    }
}

__global__ __launch_bounds__(256, 1)
void qsim_kernel(const float* __restrict__ x,
                 const float* __restrict__ w,
                 const int* __restrict__ dimA_p,
                 void* __restrict__ out_v,
                 int B, int out_size)
{
    __shared__ u64 st[NDIM];                    // packed statevector (16 KB)
    __shared__ u64 pg[NMAT][6];                 // packed gate splats (3.1 KB)
    __shared__ float2 u[NQ][2];                 // embed*YZY0 column coefs
    __shared__ int physA[32], physB[64];        // trace index tables
    __shared__ float partial[4][1024];          // trace partials (16 KB)

    const int tid = threadIdx.x;
    const int b   = blockIdx.x;

    // ---- Fused M = Ry(t2) Rz(t1) Ry(t0); store packed splats ----
    float2 al0, be0;                            // kept for embedding (tid < NQ)
    if (tid < NMAT) {
        int base = tid * 3;
        float t0 = w[base], t1 = w[base + 1], t2 = w[base + 2];
        float c0, s0, c1, s1, c2, s2;
        sincosf(0.5f * t0, &s0, &c0);
        sincosf(0.5f * t1, &s1, &c1);
        sincosf(0.5f * t2, &s2, &c2);
        float2 em = make_float2(c1, -s1);
        float2 ep = make_float2(c1,  s1);
        float2 al = make_float2( c2*c0*em.x - s2*s0*ep.x,  c2*c0*em.y - s2*s0*ep.y);
        float2 be = make_float2( s2*c0*em.x + c2*s0*ep.x,  s2*c0*em.y + c2*s0*ep.y);
        pg[tid][0] = pk(al.x, al.x);
        pg[tid][1] = pk(-al.y, al.y);
        pg[tid][2] = pk(al.y, -al.y);
        pg[tid][3] = pk(be.x, be.x);
        pg[tid][4] = pk(-be.y, be.y);
        pg[tid][5] = pk(-be.x, -be.x);
        al0 = al; be0 = be;
    }
    // ---- Embedding fused into block 0 ----
    if (tid < NQ) {
        float sh, ch;
        sincosf(0.5f * x[b * NQ + tid], &sh, &ch);
        u[tid][0] = make_float2(al0.x * ch - be0.x * sh, al0.y * ch + be0.y * sh);
        u[tid][1] = make_float2(be0.x * ch + al0.x * sh, be0.y * ch - al0.y * sh);
    }
    // ---- Trace permutation tables ----
    if (tid >= 64 && tid < 96) {
        int j = tid - 64; unsigned ph = 0;
        #pragma unroll
        for (int bit = 0; bit < 5; bit++) if ((j >> bit) & 1) ph ^= dTB.g[bit];
        physA[j] = (int)ph;
    }
    if (tid < 64) {
        int i = tid; unsigned ph = 0;
        #pragma unroll
        for (int bit = 0; bit < 6; bit++) if ((i >> bit) & 1) ph ^= dTB.g[5 + bit];
        physB[i] = (int)ph;
    }
    __syncthreads();

    // ---- Product-state init: 8 consecutive amps per thread ----
    {
        // p = (tid << 3) | k ; qubit q <-> bit (10 - q)
        float2 hi = cmul(u[0][(tid >> 7) & 1], u[1][(tid >> 6) & 1]);
        hi = cmul(hi, u[2][(tid >> 5) & 1]);
        hi = cmul(hi, u[3][(tid >> 4) & 1]);
        hi = cmul(hi, u[4][(tid >> 3) & 1]);
        hi = cmul(hi, u[5][(tid >> 2) & 1]);
        hi = cmul(hi, u[6][(tid >> 1) & 1]);
        hi = cmul(hi, u[7][tid & 1]);
        #pragma unroll
        for (int k = 0; k < 8; k++) {
            float2 lo = cmul(u[8][(k >> 2) & 1], cmul(u[9][(k >> 1) & 1], u[10][k & 1]));
            float2 r = cmul(hi, lo);
            st[(tid << 3) | k] = pk(r.x, r.y);
        }
    }
    __syncthreads();

    // ---- Blocks 1..5 ----
    do_layer<0>(st, pg, tid);
    do_layer<1>(st, pg, tid);
    do_layer<2>(st, pg, tid);
    do_layer<3>(st, pg, tid);
    do_layer<4>(st, pg, tid);

    // ---- Partial trace: Re(rho[j,k]) = sum_i Re(psi_ij psi_ik*) ----
    const int dimA = decode_dimA(dimA_p, B, out_size);
    const int dA   = 1 << dimA;
    const int dB   = NDIM >> dimA;
    const int nOut = dA * dA;
    const bool real_only = ((long long)B * nOut == (long long)out_size);

    if (dimA == 5 && real_only) {
        // 4 i-groups x 64 threads; each thread a 4x4 tile over 16 i's; packed dots
        int g  = tid >> 6;           // 0..3
        int ss = tid & 63;
        int j0 = (ss >> 3) * 4;      // 8 row-quads
        int k0 = (ss & 7) * 4;       // 8 col-quads
        int paj[4], pak[4];
        #pragma unroll
        for (int d = 0; d < 4; d++) { paj[d] = physA[j0 + d]; pak[d] = physA[k0 + d]; }
        u64 acc[4][4];
        #pragma unroll
        for (int a = 0; a < 4; a++)
            #pragma unroll
            for (int c = 0; c < 4; c++) acc[a][c] = 0ull;
        #pragma unroll
        for (int ii = 0; ii < 16; ii++) {
            int pb = physB[g * 16 + ii];
            u64 aj[4], ak[4];
            #pragma unroll
            for (int d = 0; d < 4; d++) { aj[d] = st[pb ^ paj[d]]; ak[d] = st[pb ^ pak[d]]; }
            #pragma unroll
            for (int a = 0; a < 4; a++)
                #pragma unroll
                for (int c = 0; c < 4; c++)
                    acc[a][c] = fma2(aj[a], ak[c], acc[a][c]);   // (x*x, y*y) lanes
        }
        #pragma unroll
        for (int a = 0; a < 4; a++)
            #pragma unroll
            for (int c = 0; c < 4; c++) {
                float sx, sy; upk(acc[a][c], sx, sy);
                partial[g][(j0 + a) * 32 + (k0 + c)] = sx + sy;
            }
        __syncthreads();
        #pragma unroll
        for (int m = 0; m < 4; m++) {
            int o = tid * 4 + m;
            ((float*)out_v)[b * 1024 + o] =
                partial[0][o] + partial[1][o] + partial[2][o] + partial[3][o];
        }
    } else {
        // Generic fallback (scalar)
        for (int o = tid; o < nOut; o += blockDim.x) {
            int j = o / dA;
            int k = o - j * dA;
            float2 acc = make_float2(0.f, 0.f);
            for (int i = 0; i < dB; i++) {
                int lj = i * dA + j, lk = i * dA + k;
                unsigned pj = 0, pkk = 0;
                #pragma unroll
                for (int bit = 0; bit < NQ; bit++) {
                    if ((lj >> bit) & 1) pj ^= dTB.g[bit];
                    if ((lk >> bit) & 1) pkk ^= dTB.g[bit];
                }
                float ax, ay, cx, cy;
                upk(st[pj], ax, ay);
                upk(st[pkk], cx, cy);
                acc.x = fmaf(ax, cx, fmaf(ay, cy, acc.x));
                acc.y = fmaf(ay, cx, fmaf(-ax, cy, acc.y));
            }
            if (real_only) ((float*)out_v)[b * nOut + o] = acc.x;
            else           ((float2*)out_v)[b * nOut + o] = acc;
        }
    }
}

extern "C" void kernel_launch(void* const* d_in, const int* in_sizes, int n_in,
                              void* d_out, int out_size) {
    // Bind by element count (unique sizes): w=198, dimA=1, x = B*11
    const float* x = nullptr;
    const float* w = nullptr;
    const int* dimA_p = nullptr;
    int x_size = 0;
    for (int i = 0; i < n_in; i++) {
        if (in_sizes[i] == W_SIZE) w = (const float*)d_in[i];
        else if (in_sizes[i] == 1) dimA_p = (const int*)d_in[i];
        else { x = (const float*)d_in[i]; x_size = in_sizes[i]; }
    }
    if (!x) { x = (const float*)d_in[0]; x_size = in_sizes[0]; }
    if (!w) { w = (const float*)d_in[1]; }

    int B = x_size / NQ;   // 16
    qsim_kernel<<<B, 256>>>(x, w, dimA_p, d_out, B, out_size);
}

// round 13
// speedup vs baseline: 1.6875x; 1.5280x over previous
#include <cuda_runtime.h>
#include <cuda_bf16.h>

typedef unsigned long long u64;

#define NQ 11
#define NDIM 2048                 // 1 << NQ
#define NLAYERS 5
#define NBLK (NLAYERS + 1)        // 6 YZY blocks
#define NMAT (NBLK * NQ)          // 66 fused matrices
#define W_SIZE (3 * NMAT)         // 198

// ---------- packed f32x2 helpers (FFMA2 is PTX-only on sm_103a) ----------
__device__ __forceinline__ u64 pk(float lo, float hi) {
    u64 r; asm("mov.b64 %0, {%1, %2};" : "=l"(r) : "f"(lo), "f"(hi)); return r;
}
__device__ __forceinline__ void upk(u64 v, float& lo, float& hi) {
    asm("mov.b64 {%0, %1}, %2;" : "=f"(lo), "=f"(hi) : "l"(v));
}
__device__ __forceinline__ u64 swp(u64 v) {
    float lo, hi; upk(v, lo, hi); return pk(hi, lo);
}
__device__ __forceinline__ u64 fma2(u64 a, u64 b, u64 c) {
    u64 r; asm("fma.rn.f32x2 %0, %1, %2, %3;" : "=l"(r) : "l"(a), "l"(b), "l"(c)); return r;
}
__device__ __forceinline__ u64 mul2(u64 a, u64 b) {
    u64 r; asm("mul.rn.f32x2 %0, %1, %2;" : "=l"(r) : "l"(a), "l"(b)); return r;
}

__device__ __forceinline__ float2 cmul(float2 a, float2 b) {
    return make_float2(a.x * b.x - a.y * b.y, a.x * b.y + a.y * b.x);
}

// ---------- Compile-time GF(2) CNOT-ring tracking + bank swizzle ----------
// Storage swizzle S(p) = p ^ (p>>6): invertible (unitriangular). Applied to the
// CONSTANT vectors at compile time, so all XOR-composed addresses land swizzled
// with zero runtime cost. This breaks the rank-1 lane->bank projection of the
// raw v vectors (which caused up to 16-way smem conflicts).
constexpr unsigned SWZ(unsigned x) { return x ^ (x >> 6); }
struct Tabs {
    unsigned v[NLAYERS][NQ];   // gate-axis XOR vectors (G columns), swizzled
    unsigned g[NQ];            // final G columns (trace permutation), swizzled
};
constexpr Tabs make_tabs() {
    Tabs T{};
    unsigned frow[NQ]{}, gcol[NQ]{};
    for (int i = 0; i < NQ; i++) { frow[i] = 1u << i; gcol[i] = 1u << i; }
    for (int L = 0; L < NLAYERS; L++) {
        for (int q = 0; q < NQ; q++) {
            const int bc = NQ - 1 - q;
            const int bt = NQ - 1 - ((q + 1) % NQ);
            frow[bt] ^= frow[bc];
            gcol[bc] ^= gcol[bt];
        }
        for (int q = 0; q < NQ; q++) T.v[L][q] = SWZ(gcol[NQ - 1 - q]);
    }
    for (int i = 0; i < NQ; i++) T.g[i] = SWZ(gcol[i]);
    return T;
}
constexpr Tabs TB = make_tabs();            // compile-time folded constants
__constant__ Tabs dTB = make_tabs();        // device mirror for runtime accesses

__device__ __forceinline__ int decode_dimA(const int* p, int B, int out_size) {
    int d = -1;
    if (p) {
        int v = p[0];
        if (v >= 1 && v <= NQ) d = v;
        else {
            float f = __int_as_float(v);
            if (f >= 0.5f && f <= 11.5f) d = (int)(f + 0.5f);
        }
    }
    if (d < 1 || d > NQ) {
        for (int t = 1; t <= NQ; t++) {
            long long nc = (long long)B << (2 * t);
            if (nc == (long long)out_size || 2 * nc == (long long)out_size) { d = t; break; }
        }
    }
    if (d < 1 || d > NQ) d = 5;
    return d;
}

// Packed gate splats, indices: 0=axx 1=ayy 2=cayy 3=bxx 4=byy 5=nbxx
// SU(2) gate M = [[al, -conj(be)], [be, conj(al)]]:
//   al*z       = axx*z  + ayy*swp(z)      axx=(al.x,al.x)  ayy=(-al.y, al.y)
//   conj(al)*z = axx*z  + cayy*swp(z)     cayy=(al.y,-al.y)
//   be*z       = bxx*z  + byy*swp(z)      bxx=(be.x,be.x)  byy=(-be.y, be.y)
//  -conj(be)*z = nbxx*z + byy*swp(z)      nbxx=(-be.x,-be.x)
__device__ __forceinline__ void reg_gate(u64& za, u64& zb, const u64* G) {
    u64 zas = swp(za), zbs = swp(zb);
    u64 na = fma2(G[4], zbs, fma2(G[5], zb, fma2(G[1], zas, mul2(G[0], za))));
    u64 nb = fma2(G[2], zbs, fma2(G[0], zb, fma2(G[4], zas, mul2(G[3], za))));
    za = na; zb = nb;
}

template<int MASK>
__device__ __forceinline__ void lane_gate(u64 z[4], const u64* G, int lane) {
    bool bit = (lane & MASK) != 0;
    u64 cxx = G[0];                     // al.x == conj(al).x
    u64 cyy = bit ? G[2] : G[1];        // conj(al) : al
    u64 dxx = bit ? G[3] : G[5];        // be : -conj(be)
    u64 dyy = G[4];                     // shared
    #pragma unroll
    for (int k = 0; k < 4; k++) {
        float lo, hi; upk(z[k], lo, hi);
        float plo = __shfl_xor_sync(0xffffffffu, lo, MASK);
        float phi = __shfl_xor_sync(0xffffffffu, hi, MASK);
        u64 zp = pk(plo, phi);
        z[k] = fma2(dyy, swp(zp), fma2(dxx, zp, fma2(cyy, swp(z[k]), mul2(cxx, z[k]))));
    }
}

// One YZY block (block L+1) in y-coordinates: p(y) = XOR of v_q for set y_q.
// Round 1: y0,y1 in registers; y2..y6 on lanes; y7..y10 on warps (gates q0..q6).
// Round 2: y7,y8 in registers; y9,y10,y0..y2 on lanes (gates q7..q10).
template<int L>
__device__ __forceinline__ void do_layer(u64* st, const u64 (*pg)[6], int tid) {
    constexpr unsigned v0 = TB.v[L][0],  v1 = TB.v[L][1],  v2 = TB.v[L][2];
    constexpr unsigned v3 = TB.v[L][3],  v4 = TB.v[L][4],  v5 = TB.v[L][5];
    constexpr unsigned v6 = TB.v[L][6],  v7 = TB.v[L][7],  v8 = TB.v[L][8];
    constexpr unsigned v9 = TB.v[L][9],  v10 = TB.v[L][10];
    const int lane = tid & 31, wrp = tid >> 5;
    const int mb = (L + 1) * NQ;
    u64 z[4];

    // ---- Round 1 ----
    {
        unsigned base = ((lane & 1) ? v2 : 0u) ^ ((lane & 2) ? v3 : 0u)
                      ^ ((lane & 4) ? v4 : 0u) ^ ((lane & 8) ? v5 : 0u)
                      ^ ((lane & 16) ? v6 : 0u)
                      ^ ((wrp & 1) ? v7 : 0u) ^ ((wrp & 2) ? v8 : 0u)
                      ^ ((wrp & 4) ? v9 : 0u) ^ ((wrp & 8) ? v10 : 0u);
        unsigned a0 = base, a1 = base ^ v0, a2 = base ^ v1, a3 = base ^ v0 ^ v1;
        z[0] = st[a0]; z[1] = st[a1]; z[2] = st[a2]; z[3] = st[a3];
        { const u64* G = pg[mb + 0]; reg_gate(z[0], z[1], G); reg_gate(z[2], z[3], G); }
        { const u64* G = pg[mb + 1]; reg_gate(z[0], z[2], G); reg_gate(z[1], z[3], G); }
        lane_gate<1 >(z, pg[mb + 2], lane);
        lane_gate<2 >(z, pg[mb + 3], lane);
        lane_gate<4 >(z, pg[mb + 4], lane);
        lane_gate<8 >(z, pg[mb + 5], lane);
        lane_gate<16>(z, pg[mb + 6], lane);
        st[a0] = z[0]; st[a1] = z[1]; st[a2] = z[2]; st[a3] = z[3];
        __syncthreads();
    }
    // ---- Round 2 ----
    {
        unsigned base = ((lane & 1) ? v9 : 0u) ^ ((lane & 2) ? v10 : 0u)
                      ^ ((lane & 4) ? v0 : 0u) ^ ((lane & 8) ? v1 : 0u)
                      ^ ((lane & 16) ? v2 : 0u)
                      ^ ((wrp & 1) ? v3 : 0u) ^ ((wrp & 2) ? v4 : 0u)
                      ^ ((wrp & 4) ? v5 : 0u) ^ ((wrp & 8) ? v6 : 0u);
        unsigned a0 = base, a1 = base ^ v7, a2 = base ^ v8, a3 = base ^ v7 ^ v8;
        z[0] = st[a0]; z[1] = st[a1]; z[2] = st[a2]; z[3] = st[a3];
        { const u64* G = pg[mb + 7]; reg_gate(z[0], z[1], G); reg_gate(z[2], z[3], G); }
        { const u64* G = pg[mb + 8]; reg_gate(z[0], z[2], G); reg_gate(z[1], z[3], G); }
        lane_gate<1>(z, pg[mb + 9],  lane);
        lane_gate<2>(z, pg[mb + 10], lane);
        st[a0] = z[0]; st[a1] = z[1]; st[a2] = z[2]; st[a3] = z[3];
        __syncthreads();
    }
}

__global__ __launch_bounds__(512)
void qsim_kernel(const float* __restrict__ x,
                 const float* __restrict__ w,
                 const int* __restrict__ dimA_p,
                 void* __restrict__ out_v,
                 int B, int out_size)
{
    __shared__ u64 st[NDIM];                    // packed statevector (16 KB)
    __shared__ u64 pg[NMAT][6];                 // packed gate splats (3.1 KB)
    __shared__ float2 u[NQ][2];                 // embed*YZY0 column coefs
    __shared__ int physA[32], physB[64];        // trace index tables (swizzled)
    __shared__ float partial[4][1024];          // trace partials (16 KB)

    const int tid = threadIdx.x;
    const int b   = blockIdx.x;

    // ---- Fused M = Ry(t2) Rz(t1) Ry(t0); store packed splats ----
    float2 al0, be0;                            // kept for embedding (tid < NQ)
    if (tid < NMAT) {
        int base = tid * 3;
        float t0 = w[base], t1 = w[base + 1], t2 = w[base + 2];
        float c0, s0, c1, s1, c2, s2;
        sincosf(0.5f * t0, &s0, &c0);
        sincosf(0.5f * t1, &s1, &c1);
        sincosf(0.5f * t2, &s2, &c2);
        float2 em = make_float2(c1, -s1);
        float2 ep = make_float2(c1,  s1);
        float2 al = make_float2( c2*c0*em.x - s2*s0*ep.x,  c2*c0*em.y - s2*s0*ep.y);
        float2 be = make_float2( s2*c0*em.x + c2*s0*ep.x,  s2*c0*em.y + c2*s0*ep.y);
        pg[tid][0] = pk(al.x, al.x);
        pg[tid][1] = pk(-al.y, al.y);
        pg[tid][2] = pk(al.y, -al.y);
        pg[tid][3] = pk(be.x, be.x);
        pg[tid][4] = pk(-be.y, be.y);
        pg[tid][5] = pk(-be.x, -be.x);
        al0 = al; be0 = be;
    }
    // ---- Embedding fused into block 0 ----
    if (tid < NQ) {
        float sh, ch;
        sincosf(0.5f * x[b * NQ + tid], &sh, &ch);
        u[tid][0] = make_float2(al0.x * ch - be0.x * sh, al0.y * ch + be0.y * sh);
        u[tid][1] = make_float2(be0.x * ch + al0.x * sh, be0.y * ch - al0.y * sh);
    }
    // ---- Trace permutation tables (dTB.g is pre-swizzled) ----
    if (tid >= 64 && tid < 96) {
        int j = tid - 64; unsigned ph = 0;
        #pragma unroll
        for (int bit = 0; bit < 5; bit++) if ((j >> bit) & 1) ph ^= dTB.g[bit];
        physA[j] = (int)ph;
    }
    if (tid < 64) {
        int i = tid; unsigned ph = 0;
        #pragma unroll
        for (int bit = 0; bit < 6; bit++) if ((i >> bit) & 1) ph ^= dTB.g[5 + bit];
        physB[i] = (int)ph;
    }
    __syncthreads();

    // ---- Product-state init: amp p stored at S(p) = p ^ (p>>6) ----
    {
        float2 hi = cmul(u[0][(tid >> 8) & 1], u[1][(tid >> 7) & 1]);
        hi = cmul(hi, u[2][(tid >> 6) & 1]);
        hi = cmul(hi, u[3][(tid >> 5) & 1]);
        hi = cmul(hi, u[4][(tid >> 4) & 1]);
        hi = cmul(hi, u[5][(tid >> 3) & 1]);
        hi = cmul(hi, u[6][(tid >> 2) & 1]);
        hi = cmul(hi, u[7][(tid >> 1) & 1]);
        hi = cmul(hi, u[8][tid & 1]);
        #pragma unroll
        for (int k = 0; k < 4; k++) {
            float2 lo = cmul(u[9][(k >> 1) & 1], u[10][k & 1]);
            float2 r = cmul(hi, lo);
            unsigned p = (unsigned)((tid << 2) | k);
            st[p ^ (p >> 6)] = pk(r.x, r.y);
        }
    }
    __syncthreads();

    // ---- Blocks 1..5 ----
    do_layer<0>(st, pg, tid);
    do_layer<1>(st, pg, tid);
    do_layer<2>(st, pg, tid);
    do_layer<3>(st, pg, tid);
    do_layer<4>(st, pg, tid);

    // ---- Partial trace: Re(rho[j,k]) = sum_i Re(psi_ij psi_ik*) ----
    const int dimA = decode_dimA(dimA_p, B, out_size);
    const int dA   = 1 << dimA;
    const int dB   = NDIM >> dimA;
    const int nOut = dA * dA;
    const bool real_only = ((long long)B * nOut == (long long)out_size);

    if (dimA == 5 && real_only) {
        // 4 i-groups x 128 threads; each thread a 2x4 tile over 16 i's; packed dots
        int g  = tid >> 7;
        int ss = tid & 127;
        int j0 = (ss >> 3) * 2;
        int k0 = (ss & 7) * 4;
        int paj0 = physA[j0], paj1 = physA[j0 + 1];
        int pak[4];
        #pragma unroll
        for (int d = 0; d < 4; d++) pak[d] = physA[k0 + d];
        u64 acc2[2][4];
        #pragma unroll
        for (int a = 0; a < 2; a++)
            #pragma unroll
            for (int c = 0; c < 4; c++) acc2[a][c] = 0ull;
        #pragma unroll
        for (int ii = 0; ii < 16; ii++) {
            int pb = physB[g * 16 + ii];
            u64 aj0 = st[pb ^ paj0];
            u64 aj1 = st[pb ^ paj1];
            #pragma unroll
            for (int c = 0; c < 4; c++) {
                u64 ak = st[pb ^ pak[c]];
                acc2[0][c] = fma2(aj0, ak, acc2[0][c]);   // (x*x, y*y) lanes
                acc2[1][c] = fma2(aj1, ak, acc2[1][c]);
            }
        }
        #pragma unroll
        for (int a = 0; a < 2; a++)
            #pragma unroll
            for (int c = 0; c < 4; c++) {
                float sx, sy; upk(acc2[a][c], sx, sy);
                partial[g][(j0 + a) * 32 + (k0 + c)] = sx + sy;
            }
        __syncthreads();
        #pragma unroll
        for (int m = 0; m < 2; m++) {
            int o = tid * 2 + m;
            ((float*)out_v)[b * 1024 + o] =
                partial[0][o] + partial[1][o] + partial[2][o] + partial[3][o];
        }
    } else {
        // Generic fallback (scalar)
        for (int o = tid; o < nOut; o += blockDim.x) {
            int j = o / dA;
            int k = o - j * dA;
            float2 acc = make_float2(0.f, 0.f);
            for (int i = 0; i < dB; i++) {
                int lj = i * dA + j, lk = i * dA + k;
                unsigned pj = 0, pkk = 0;
                #pragma unroll
                for (int bit = 0; bit < NQ; bit++) {
                    if ((lj >> bit) & 1) pj ^= dTB.g[bit];
                    if ((lk >> bit) & 1) pkk ^= dTB.g[bit];
                }
                float ax, ay, cx, cy;
                upk(st[pj], ax, ay);
                upk(st[pkk], cx, cy);
                acc.x = fmaf(ax, cx, fmaf(ay, cy, acc.x));
                acc.y = fmaf(ay, cx, fmaf(-ax, cy, acc.y));
            }
            if (real_only) ((float*)out_v)[b * nOut + o] = acc.x;
            else           ((float2*)out_v)[b * nOut + o] = acc;
        }
    }
}

extern "C" void kernel_launch(void* const* d_in, const int* in_sizes, int n_in,
                              void* d_out, int out_size) {
    // Bind by element count (unique sizes): w=198, dimA=1, x = B*11
    const float* x = nullptr;
    const float* w = nullptr;
    const int* dimA_p = nullptr;
    int x_size = 0;
    for (int i = 0; i < n_in; i++) {
        if (in_sizes[i] == W_SIZE) w = (const float*)d_in[i];
        else if (in_sizes[i] == 1) dimA_p = (const int*)d_in[i];
        else { x = (const float*)d_in[i]; x_size = in_sizes[i]; }
    }
    if (!x) { x = (const float*)d_in[0]; x_size = in_sizes[0]; }
    if (!w) { w = (const float*)d_in[1]; }

    int B = x_size / NQ;   // 16
    qsim_kernel<<<B, 512>>>(x, w, dimA_p, d_out, B, out_size);
}

// round 14
// speedup vs baseline: 1.6911x; 1.0022x over previous
#include <cuda_runtime.h>
#include <cuda_bf16.h>

typedef unsigned long long u64;

#define NQ 11
#define NDIM 2048                 // 1 << NQ
#define NLAYERS 5
#define NBLK (NLAYERS + 1)        // 6 YZY blocks
#define NMAT (NBLK * NQ)          // 66 fused matrices
#define W_SIZE (3 * NMAT)         // 198

// ---------- packed f32x2 helpers (FFMA2 is PTX-only on sm_103a) ----------
__device__ __forceinline__ u64 pk(float lo, float hi) {
    u64 r; asm("mov.b64 %0, {%1, %2};" : "=l"(r) : "f"(lo), "f"(hi)); return r;
}
__device__ __forceinline__ void upk(u64 v, float& lo, float& hi) {
    asm("mov.b64 {%0, %1}, %2;" : "=f"(lo), "=f"(hi) : "l"(v));
}
__device__ __forceinline__ u64 fma2(u64 a, u64 b, u64 c) {
    u64 r; asm("fma.rn.f32x2 %0, %1, %2, %3;" : "=l"(r) : "l"(a), "l"(b), "l"(c)); return r;
}
__device__ __forceinline__ u64 mul2(u64 a, u64 b) {
    u64 r; asm("mul.rn.f32x2 %0, %1, %2;" : "=l"(r) : "l"(a), "l"(b)); return r;
}

__device__ __forceinline__ float2 cmul(float2 a, float2 b) {
    return make_float2(a.x * b.x - a.y * b.y, a.x * b.y + a.y * b.x);
}

// ---------- Compile-time GF(2) CNOT-ring tracking + bank swizzle ----------
// Storage swizzle S(p) = p ^ (p>>6): invertible (unitriangular). Applied to the
// CONSTANT vectors at compile time, so all XOR-composed addresses land swizzled
// with zero runtime cost. Breaks the rank-1 lane->bank projection of the raw
// v vectors (which caused up to 16-way smem conflicts).
constexpr unsigned SWZ(unsigned x) { return x ^ (x >> 6); }
struct Tabs {
    unsigned v[NLAYERS][NQ];   // gate-axis XOR vectors (G columns), swizzled
    unsigned g[NQ];            // final G columns (trace permutation), swizzled
};
constexpr Tabs make_tabs() {
    Tabs T{};
    unsigned frow[NQ]{}, gcol[NQ]{};
    for (int i = 0; i < NQ; i++) { frow[i] = 1u << i; gcol[i] = 1u << i; }
    for (int L = 0; L < NLAYERS; L++) {
        for (int q = 0; q < NQ; q++) {
            const int bc = NQ - 1 - q;
            const int bt = NQ - 1 - ((q + 1) % NQ);
            frow[bt] ^= frow[bc];
            gcol[bc] ^= gcol[bt];
        }
        for (int q = 0; q < NQ; q++) T.v[L][q] = SWZ(gcol[NQ - 1 - q]);
    }
    for (int i = 0; i < NQ; i++) T.g[i] = SWZ(gcol[i]);
    return T;
}
constexpr Tabs TB = make_tabs();            // compile-time folded constants
__constant__ Tabs dTB = make_tabs();        // device mirror for runtime accesses

__device__ __forceinline__ int decode_dimA(const int* p, int B, int out_size) {
    int d = -1;
    if (p) {
        int v = p[0];
        if (v >= 1 && v <= NQ) d = v;
        else {
            float f = __int_as_float(v);
            if (f >= 0.5f && f <= 11.5f) d = (int)(f + 0.5f);
        }
    }
    if (d < 1 || d > NQ) {
        for (int t = 1; t <= NQ; t++) {
            long long nc = (long long)B << (2 * t);
            if (nc == (long long)out_size || 2 * nc == (long long)out_size) { d = t; break; }
        }
    }
    if (d < 1 || d > NQ) d = 5;
    return d;
}

// Packed gate splats, indices: 0=axx 1=ayy 2=cayy 3=bxx 4=byy 5=nbxx
// SU(2) gate M = [[al, -conj(be)], [be, conj(al)]]:
//   al*z       = axx*z  + ayy*swap(z)     axx=(al.x,al.x)  ayy=(-al.y, al.y)
//   conj(al)*z = axx*z  + cayy*swap(z)    cayy=(al.y,-al.y)
//   be*z       = bxx*z  + byy*swap(z)     bxx=(be.x,be.x)  byy=(-be.y, be.y)
//  -conj(be)*z = nbxx*z + byy*swap(z)     nbxx=(-be.x,-be.x)
__device__ __forceinline__ void reg_gate(u64& za, u64& zb, const u64* G) {
    float zax, zay, zbx, zby;
    upk(za, zax, zay);
    upk(zb, zbx, zby);
    u64 zas = pk(zay, zax);
    u64 zbs = pk(zby, zbx);
    u64 na = fma2(G[4], zbs, fma2(G[5], zb, fma2(G[1], zas, mul2(G[0], za))));
    u64 nb = fma2(G[2], zbs, fma2(G[0], zb, fma2(G[4], zas, mul2(G[3], za))));
    za = na; zb = nb;
}

// Lane gate: all packed operands built directly from scalar floats — exactly
// one unpack and three packs per amp, no upk(pk(...)) chains.
template<int MASK>
__device__ __forceinline__ void lane_gate(u64 z[4], const u64* G, int lane) {
    bool bit = (lane & MASK) != 0;
    u64 cxx = G[0];                     // al.x == conj(al).x
    u64 cyy = bit ? G[2] : G[1];        // conj(al) : al
    u64 dxx = bit ? G[3] : G[5];        // be : -conj(be)
    u64 dyy = G[4];                     // shared
    #pragma unroll
    for (int k = 0; k < 4; k++) {
        float lo, hi; upk(z[k], lo, hi);
        float plo = __shfl_xor_sync(0xffffffffu, lo, MASK);
        float phi = __shfl_xor_sync(0xffffffffu, hi, MASK);
        u64 zsw  = pk(hi, lo);          // swap(z[k]) from existing scalars
        u64 zp   = pk(plo, phi);        // partner
        u64 zpsw = pk(phi, plo);        // swap(partner) from existing scalars
        z[k] = fma2(dyy, zpsw, fma2(dxx, zp, fma2(cyy, zsw, mul2(cxx, z[k]))));
    }
}

// One YZY block (block L+1) in y-coordinates: p(y) = XOR of v_q for set y_q.
// Round 1: y0,y1 in registers; y2..y6 on lanes; y7..y10 on warps (gates q0..q6).
// Round 2: y7,y8 in registers; y9,y10,y0..y2 on lanes (gates q7..q10).
template<int L>
__device__ __forceinline__ void do_layer(u64* st, const u64 (*pg)[6], int tid) {
    constexpr unsigned v0 = TB.v[L][0],  v1 = TB.v[L][1],  v2 = TB.v[L][2];
    constexpr unsigned v3 = TB.v[L][3],  v4 = TB.v[L][4],  v5 = TB.v[L][5];
    constexpr unsigned v6 = TB.v[L][6],  v7 = TB.v[L][7],  v8 = TB.v[L][8];
    constexpr unsigned v9 = TB.v[L][9],  v10 = TB.v[L][10];
    const int lane = tid & 31, wrp = tid >> 5;
    const int mb = (L + 1) * NQ;
    u64 z[4];

    // ---- Round 1 ----
    {
        unsigned base = ((lane & 1) ? v2 : 0u) ^ ((lane & 2) ? v3 : 0u)
                      ^ ((lane & 4) ? v4 : 0u) ^ ((lane & 8) ? v5 : 0u)
                      ^ ((lane & 16) ? v6 : 0u)
                      ^ ((wrp & 1) ? v7 : 0u) ^ ((wrp & 2) ? v8 : 0u)
                      ^ ((wrp & 4) ? v9 : 0u) ^ ((wrp & 8) ? v10 : 0u);
        unsigned a0 = base, a1 = base ^ v0, a2 = base ^ v1, a3 = base ^ v0 ^ v1;
        z[0] = st[a0]; z[1] = st[a1]; z[2] = st[a2]; z[3] = st[a3];
        { const u64* G = pg[mb + 0]; reg_gate(z[0], z[1], G); reg_gate(z[2], z[3], G); }
        { const u64* G = pg[mb + 1]; reg_gate(z[0], z[2], G); reg_gate(z[1], z[3], G); }
        lane_gate<1 >(z, pg[mb + 2], lane);
        lane_gate<2 >(z, pg[mb + 3], lane);
        lane_gate<4 >(z, pg[mb + 4], lane);
        lane_gate<8 >(z, pg[mb + 5], lane);
        lane_gate<16>(z, pg[mb + 6], lane);
        st[a0] = z[0]; st[a1] = z[1]; st[a2] = z[2]; st[a3] = z[3];
        __syncthreads();
    }
    // ---- Round 2 ----
    {
        unsigned base = ((lane & 1) ? v9 : 0u) ^ ((lane & 2) ? v10 : 0u)
                      ^ ((lane & 4) ? v0 : 0u) ^ ((lane & 8) ? v1 : 0u)
                      ^ ((lane & 16) ? v2 : 0u)
                      ^ ((wrp & 1) ? v3 : 0u) ^ ((wrp & 2) ? v4 : 0u)
                      ^ ((wrp & 4) ? v5 : 0u) ^ ((wrp & 8) ? v6 : 0u);
        unsigned a0 = base, a1 = base ^ v7, a2 = base ^ v8, a3 = base ^ v7 ^ v8;
        z[0] = st[a0]; z[1] = st[a1]; z[2] = st[a2]; z[3] = st[a3];
        { const u64* G = pg[mb + 7]; reg_gate(z[0], z[1], G); reg_gate(z[2], z[3], G); }
        { const u64* G = pg[mb + 8]; reg_gate(z[0], z[2], G); reg_gate(z[1], z[3], G); }
        lane_gate<1>(z, pg[mb + 9],  lane);
        lane_gate<2>(z, pg[mb + 10], lane);
        st[a0] = z[0]; st[a1] = z[1]; st[a2] = z[2]; st[a3] = z[3];
        __syncthreads();
    }
}

__global__ __launch_bounds__(512)
void qsim_kernel(const float* __restrict__ x,
                 const float* __restrict__ w,
                 const int* __restrict__ dimA_p,
                 void* __restrict__ out_v,
                 int B, int out_size)
{
    __shared__ u64 st[NDIM];                    // packed statevector (16 KB)
    __shared__ u64 pg[NMAT][6];                 // packed gate splats (3.1 KB)
    __shared__ float2 u[NQ][2];                 // embed*YZY0 column coefs
    __shared__ int physA[32], physB[64];        // trace index tables (swizzled)
    __shared__ float partial[4][1024];          // trace partials (16 KB)

    const int tid = threadIdx.x;
    const int b   = blockIdx.x;

    // ---- Fused M = Ry(t2) Rz(t1) Ry(t0); store packed splats ----
    float2 al0, be0;                            // kept for embedding (tid < NQ)
    if (tid < NMAT) {
        int base = tid * 3;
        float t0 = w[base], t1 = w[base + 1], t2 = w[base + 2];
        float c0, s0, c1, s1, c2, s2;
        sincosf(0.5f * t0, &s0, &c0);
        sincosf(0.5f * t1, &s1, &c1);
        sincosf(0.5f * t2, &s2, &c2);
        float2 em = make_float2(c1, -s1);
        float2 ep = make_float2(c1,  s1);
        float2 al = make_float2( c2*c0*em.x - s2*s0*ep.x,  c2*c0*em.y - s2*s0*ep.y);
        float2 be = make_float2( s2*c0*em.x + c2*s0*ep.x,  s2*c0*em.y + c2*s0*ep.y);
        pg[tid][0] = pk(al.x, al.x);
        pg[tid][1] = pk(-al.y, al.y);
        pg[tid][2] = pk(al.y, -al.y);
        pg[tid][3] = pk(be.x, be.x);
        pg[tid][4] = pk(-be.y, be.y);
        pg[tid][5] = pk(-be.x, -be.x);
        al0 = al; be0 = be;
    }
    // ---- Embedding fused into block 0 ----
    if (tid < NQ) {
        float sh, ch;
        sincosf(0.5f * x[b * NQ + tid], &sh, &ch);
        u[tid][0] = make_float2(al0.x * ch - be0.x * sh, al0.y * ch + be0.y * sh);
        u[tid][1] = make_float2(be0.x * ch + al0.x * sh, be0.y * ch - al0.y * sh);
    }
    // ---- Trace permutation tables (dTB.g is pre-swizzled) ----
    if (tid >= 64 && tid < 96) {
        int j = tid - 64; unsigned ph = 0;
        #pragma unroll
        for (int bit = 0; bit < 5; bit++) if ((j >> bit) & 1) ph ^= dTB.g[bit];
        physA[j] = (int)ph;
    }
    if (tid < 64) {
        int i = tid; unsigned ph = 0;
        #pragma unroll
        for (int bit = 0; bit < 6; bit++) if ((i >> bit) & 1) ph ^= dTB.g[5 + bit];
        physB[i] = (int)ph;
    }
    __syncthreads();

    // ---- Product-state init: amp p stored at S(p) = p ^ (p>>6) ----
    {
        float2 hi = cmul(u[0][(tid >> 8) & 1], u[1][(tid >> 7) & 1]);
        hi = cmul(hi, u[2][(tid >> 6) & 1]);
        hi = cmul(hi, u[3][(tid >> 5) & 1]);
        hi = cmul(hi, u[4][(tid >> 4) & 1]);
        hi = cmul(hi, u[5][(tid >> 3) & 1]);
        hi = cmul(hi, u[6][(tid >> 2) & 1]);
        hi = cmul(hi, u[7][(tid >> 1) & 1]);
        hi = cmul(hi, u[8][tid & 1]);
        #pragma unroll
        for (int k = 0; k < 4; k++) {
            float2 lo = cmul(u[9][(k >> 1) & 1], u[10][k & 1]);
            float2 r = cmul(hi, lo);
            unsigned p = (unsigned)((tid << 2) | k);
            st[p ^ (p >> 6)] = pk(r.x, r.y);
        }
    }
    __syncthreads();

    // ---- Blocks 1..5 ----
    do_layer<0>(st, pg, tid);
    do_layer<1>(st, pg, tid);
    do_layer<2>(st, pg, tid);
    do_layer<3>(st, pg, tid);
    do_layer<4>(st, pg, tid);

    // ---- Partial trace: Re(rho[j,k]) = sum_i Re(psi_ij psi_ik*) ----
    const int dimA = decode_dimA(dimA_p, B, out_size);
    const int dA   = 1 << dimA;
    const int dB   = NDIM >> dimA;
    const int nOut = dA * dA;
    const bool real_only = ((long long)B * nOut == (long long)out_size);

    if (dimA == 5 && real_only) {
        // 4 i-groups x 128 threads; each thread a 2x4 tile over 16 i's; packed dots
        int g  = tid >> 7;
        int ss = tid & 127;
        int j0 = (ss >> 3) * 2;
        int k0 = (ss & 7) * 4;
        int paj0 = physA[j0], paj1 = physA[j0 + 1];
        int pak[4];
        #pragma unroll
        for (int d = 0; d < 4; d++) pak[d] = physA[k0 + d];
        u64 acc2[2][4];
        #pragma unroll
        for (int a = 0; a < 2; a++)
            #pragma unroll
            for (int c = 0; c < 4; c++) acc2[a][c] = 0ull;
        #pragma unroll
        for (int ii = 0; ii < 16; ii++) {
            int pb = physB[g * 16 + ii];
            u64 aj0 = st[pb ^ paj0];
            u64 aj1 = st[pb ^ paj1];
            #pragma unroll
            for (int c = 0; c < 4; c++) {
                u64 ak = st[pb ^ pak[c]];
                acc2[0][c] = fma2(aj0, ak, acc2[0][c]);   // (x*x, y*y) lanes
                acc2[1][c] = fma2(aj1, ak, acc2[1][c]);
            }
        }
        #pragma unroll
        for (int a = 0; a < 2; a++)
            #pragma unroll
            for (int c = 0; c < 4; c++) {
                float sx, sy; upk(acc2[a][c], sx, sy);
                partial[g][(j0 + a) * 32 + (k0 + c)] = sx + sy;
            }
        __syncthreads();
        #pragma unroll
        for (int m = 0; m < 2; m++) {
            int o = tid * 2 + m;
            ((float*)out_v)[b * 1024 + o] =
                partial[0][o] + partial[1][o] + partial[2][o] + partial[3][o];
        }
    } else {
        // Generic fallback (scalar)
        for (int o = tid; o < nOut; o += blockDim.x) {
            int j = o / dA;
            int k = o - j * dA;
            float2 acc = make_float2(0.f, 0.f);
            for (int i = 0; i < dB; i++) {
                int lj = i * dA + j, lk = i * dA + k;
                unsigned pj = 0, pkk = 0;
                #pragma unroll
                for (int bit = 0; bit < NQ; bit++) {
                    if ((lj >> bit) & 1) pj ^= dTB.g[bit];
                    if ((lk >> bit) & 1) pkk ^= dTB.g[bit];
                }
                float ax, ay, cx, cy;
                upk(st[pj], ax, ay);
                upk(st[pkk], cx, cy);
                acc.x = fmaf(ax, cx, fmaf(ay, cy, acc.x));
                acc.y = fmaf(ay, cx, fmaf(-ax, cy, acc.y));
            }
            if (real_only) ((float*)out_v)[b * nOut + o] = acc.x;
            else           ((float2*)out_v)[b * nOut + o] = acc;
        }
    }
}

extern "C" void kernel_launch(void* const* d_in, const int* in_sizes, int n_in,
                              void* d_out, int out_size) {
    // Bind by element count (unique sizes): w=198, dimA=1, x = B*11
    const float* x = nullptr;
    const float* w = nullptr;
    const int* dimA_p = nullptr;
    int x_size = 0;
    for (int i = 0; i < n_in; i++) {
        if (in_sizes[i] == W_SIZE) w = (const float*)d_in[i];
        else if (in_sizes[i] == 1) dimA_p = (const int*)d_in[i];
        else { x = (const float*)d_in[i]; x_size = in_sizes[i]; }
    }
    if (!x) { x = (const float*)d_in[0]; x_size = in_sizes[0]; }
    if (!w) { w = (const float*)d_in[1]; }

    int B = x_size / NQ;   // 16
    qsim_kernel<<<B, 512>>>(x, w, dimA_p, d_out, B, out_size);
}